// round 1
// baseline (speedup 1.0000x reference)
#include <cuda_runtime.h>

typedef unsigned long long u64;

#define B_SZ   256
#define F_SZ   128
#define NLAYER 4
#define T_SZ   2048
#define DEPTHD 6
#define C_SZ   100
#define L_SZ   64
#define NTREE  (NLAYER * T_SZ)            /* 8192 */
#define KTOT   ((size_t)NTREE * L_SZ)     /* 524288 */
#define TPB    16                         /* trees per block */
#define NBLK   (NTREE / TPB)              /* 512 */

/* scratch: fv[tree][d][b], 4*2048*6*256 floats = 50.3 MB */
__device__ float g_fv[NTREE * DEPTHD * B_SZ];

/* ---------- f32x2 packed-math helpers (sm_103a) ---------- */
__device__ __forceinline__ u64 pack2(float a, float b) {
    u64 r; asm("mov.b64 %0, {%1, %2};" : "=l"(r) : "f"(a), "f"(b)); return r;
}
__device__ __forceinline__ void unpack2(u64 v, float &a, float &b) {
    asm("mov.b64 {%0, %1}, %2;" : "=f"(a), "=f"(b) : "l"(v));
}
__device__ __forceinline__ u64 mul2(u64 a, u64 b) {
    u64 r; asm("mul.rn.f32x2 %0, %1, %2;" : "=l"(r) : "l"(a), "l"(b)); return r;
}
__device__ __forceinline__ u64 fma2(u64 a, u64 b, u64 c) {
    u64 r; asm("fma.rn.f32x2 %0, %1, %2, %3;" : "=l"(r) : "l"(a), "l"(b), "l"(c)); return r;
}

/* ---------- kernel 0: out[b][c] = out_b[c] ---------- */
__global__ void init_out_kernel(const float* __restrict__ ob, float* __restrict__ out) {
    int i = blockIdx.x * 256 + threadIdx.x;
    if (i < B_SZ * C_SZ) out[i] = ob[i % C_SZ];
}

/* ---------- kernel 1: selector GEMM + sigmoid ----------
 * fv[m][b] = sigmoid( sel_W[m,:] . x[b,:] + sel_b[m] ),  m = tree*6+d (flat row)
 * M=49152, N=256, K=128. BM=64, BN=64, BK=64, 256 threads, 4x4 micro-tile. */
__global__ void __launch_bounds__(256) sel_kernel(const float* __restrict__ x,
                                                  const float* __restrict__ selW,
                                                  const float* __restrict__ selb) {
    __shared__ float As[64 * 65];
    __shared__ float Bs[64 * 65];
    int tid  = threadIdx.x;
    int row0 = blockIdx.x * 64;   /* m */
    int col0 = blockIdx.y * 64;   /* b */
    int tm = tid & 15, tn = tid >> 4;
    float acc[4][4];
#pragma unroll
    for (int r = 0; r < 4; r++)
#pragma unroll
        for (int s = 0; s < 4; s++) acc[r][s] = 0.f;

    for (int kt = 0; kt < 2; kt++) {
        __syncthreads();
#pragma unroll
        for (int it = 0; it < 16; it++) {
            int e = tid + it * 256;
            int r = e >> 6, kk = e & 63;
            As[r * 65 + kk] = selW[(size_t)(row0 + r) * F_SZ + kt * 64 + kk];
            Bs[r * 65 + kk] = x[(size_t)(col0 + r) * F_SZ + kt * 64 + kk];
        }
        __syncthreads();
#pragma unroll 8
        for (int kk = 0; kk < 64; kk++) {
            float a[4], b[4];
#pragma unroll
            for (int r = 0; r < 4; r++) a[r] = As[(tm * 4 + r) * 65 + kk];
#pragma unroll
            for (int s = 0; s < 4; s++) b[s] = Bs[(tn * 4 + s) * 65 + kk];
#pragma unroll
            for (int r = 0; r < 4; r++)
#pragma unroll
                for (int s = 0; s < 4; s++) acc[r][s] += a[r] * b[s];
        }
    }
#pragma unroll
    for (int r = 0; r < 4; r++) {
        int m = row0 + tm * 4 + r;
        float bias = selb[m];
        float4 o;
        o.x = 1.f / (1.f + __expf(-(acc[r][0] + bias)));
        o.y = 1.f / (1.f + __expf(-(acc[r][1] + bias)));
        o.z = 1.f / (1.f + __expf(-(acc[r][2] + bias)));
        o.w = 1.f / (1.f + __expf(-(acc[r][3] + bias)));
        *(float4*)(&g_fv[(size_t)m * B_SZ + col0 + tn * 4]) = o;
    }
}

/* ---------- kernel 2: fused leaf expansion + output GEMM ----------
 * Each block: 16 trees, ALL 256 b, ALL 100 c (so out_W read exactly once).
 * Thread (bq=tid>>2, cq=tid&3): accumulates b in {4bq..4bq+3} (2 f32x2 pairs)
 * x c in {25cq..25cq+24}  -> 50 packed accumulators.
 * Smem: Wsm[c*65+l] = (w,w) duplicated pairs; Lsm[pair*65+l] = (leaf_b0,leaf_b1).
 * Stride 65 (u64) -> inner LDS.64 conflict-free (4 distinct banks + broadcast). */
__global__ void __launch_bounds__(256, 1) accum_kernel(const float* __restrict__ outW,
                                                       float* __restrict__ out) {
    extern __shared__ u64 sm[];
    u64* Wsm = sm;                 /* 100*65 = 6500 u64 */
    u64* Lsm = sm + 6500;          /* 128*65 = 8320 u64 */

    int tid = threadIdx.x;
    int cq  = tid & 3;             /* c group: 25 c each */
    int bq  = tid >> 2;            /* b group: 4 b each  */
    int pr  = tid >> 1;            /* staging pair 0..127 */
    int lh  = tid & 1;             /* staging l-half (bit5 of l = d0 bit) */

    u64 acc[2][25];
#pragma unroll
    for (int q = 0; q < 2; q++)
#pragma unroll
        for (int j = 0; j < 25; j++) acc[q][j] = 0ull;

    int tree0 = blockIdx.x * TPB;
    for (int tt = 0; tt < TPB; tt++) {
        int tree = tree0 + tt;
        __syncthreads();

        /* --- stage W slice: out_W[c][tree*64 + l], duplicated into both f32x2 lanes --- */
        {
            const float* wp = outW + (size_t)tree * L_SZ;
#pragma unroll
            for (int k = 0; k < 25; k++) {
                int e = tid + k * 256;           /* 6400 elements */
                int c = e >> 6, l = e & 63;
                float w = wp[(size_t)c * KTOT + l];
                Wsm[c * 65 + l] = pack2(w, w);
            }
        }

        /* --- stage leaf tile: thread owns pair pr, l-half lh (32 leaves) ---
         * bits: l bit5=d0 (handled by lh), bit4..bit0 = d1..d5; bit==0 -> p, bit==1 -> 1-p */
        {
            const float* fv = g_fv + (size_t)tree * (DEPTHD * B_SZ) + pr * 2;
            u64 s0[DEPTHD], s1[DEPTHD];
#pragma unroll
            for (int d = 0; d < DEPTHD; d++) {
                float2 v = *(const float2*)(fv + d * B_SZ);
                s0[d] = pack2(v.x, v.y);
                s1[d] = pack2(1.f - v.x, 1.f - v.y);
            }
            u64 g0 = lh ? s1[0] : s0[0];
            u64 p1[2];
            p1[0] = mul2(g0, s0[1]); p1[1] = mul2(g0, s1[1]);
            u64 p2a[4];
#pragma unroll
            for (int i = 0; i < 2; i++) { p2a[i*2] = mul2(p1[i], s0[2]); p2a[i*2+1] = mul2(p1[i], s1[2]); }
            u64 p3[8];
#pragma unroll
            for (int i = 0; i < 4; i++) { p3[i*2] = mul2(p2a[i], s0[3]); p3[i*2+1] = mul2(p2a[i], s1[3]); }
            u64 p4[16];
#pragma unroll
            for (int i = 0; i < 8; i++) { p4[i*2] = mul2(p3[i], s0[4]); p4[i*2+1] = mul2(p3[i], s1[4]); }
            u64* lrow = Lsm + pr * 65 + lh * 32;
#pragma unroll
            for (int i = 0; i < 16; i++) {
                lrow[i * 2]     = mul2(p4[i], s0[5]);
                lrow[i * 2 + 1] = mul2(p4[i], s1[5]);
            }
        }
        __syncthreads();

        /* --- accumulate: per l, 2 leaf LDS.64 + 25 W LDS.64 + 50 FFMA2 --- */
        {
            const u64* l0 = Lsm + (bq * 2) * 65;
            const u64* l1 = l0 + 65;
            const u64* wbase = Wsm + cq * 25 * 65;
#pragma unroll 4
            for (int l = 0; l < 64; l++) {
                u64 lf0 = l0[l];
                u64 lf1 = l1[l];
                const u64* wrow = wbase + l;
#pragma unroll
                for (int j = 0; j < 25; j++) {
                    u64 w = wrow[j * 65];
                    acc[0][j] = fma2(lf0, w, acc[0][j]);
                    acc[1][j] = fma2(lf1, w, acc[1][j]);
                }
            }
        }
    }

    /* --- epilogue: scatter-add into out[b][c] --- */
#pragma unroll
    for (int q = 0; q < 2; q++) {
        int b = bq * 4 + q * 2;
#pragma unroll
        for (int j = 0; j < 25; j++) {
            float lo, hi;
            unpack2(acc[q][j], lo, hi);
            int c = cq * 25 + j;
            atomicAdd(&out[b * C_SZ + c], lo);
            atomicAdd(&out[(b + 1) * C_SZ + c], hi);
        }
    }
}

extern "C" void kernel_launch(void* const* d_in, const int* in_sizes, int n_in,
                              void* d_out, int out_size) {
    const float* x    = (const float*)d_in[0];
    const float* selW = (const float*)d_in[1];
    const float* selb = (const float*)d_in[2];
    const float* outW = (const float*)d_in[3];
    const float* outb = (const float*)d_in[4];
    float* out = (float*)d_out;

    init_out_kernel<<<(B_SZ * C_SZ + 255) / 256, 256>>>(outb, out);

    dim3 g1(768, 4);  /* 49152/64 m-tiles x 256/64 b-tiles */
    sel_kernel<<<g1, 256>>>(x, selW, selb);

    size_t shmem = (size_t)(6500 + 8320) * sizeof(u64);  /* 118560 B */
    cudaFuncSetAttribute(accum_kernel, cudaFuncAttributeMaxDynamicSharedMemorySize, (int)shmem);
    accum_kernel<<<NBLK, 256, shmem>>>(outW, out);
}

// round 3
// speedup vs baseline: 3.7680x; 3.7680x over previous
#include <cuda_runtime.h>
#include <cstdint>

#define B_SZ   256
#define F_SZ   128
#define DEPTHD 6
#define C_SZ   100
#define L_SZ   64
#define NTREE  8192
#define KTOT   ((size_t)NTREE * L_SZ)     /* 524288 */
#define NSLICE 74                         /* 148 CTAs = 74 slices x 2 b-halves */
#define N_PAD  112                        /* C padded: 14 n-tiles of 8 */
#define AST    68                         /* smem row stride in words: 4g+c bank-perfect */

/* scratch: fv[m = tree*6+d][b], 49152 x 256 floats = 50.3 MB */
__device__ float g_fv[NTREE * DEPTHD * B_SZ];

/* ---- tf32 helpers (baseline PTX, valid on sm_103 non-a) ---- */
__device__ __forceinline__ uint32_t f2tf(float f) {
    uint32_t u; asm("cvt.rna.tf32.f32 %0, %1;" : "=r"(u) : "f"(f)); return u;
}
__device__ __forceinline__ void mma8(float c[4],
                                     uint32_t a0, uint32_t a1, uint32_t a2, uint32_t a3,
                                     uint32_t b0, uint32_t b1) {
    asm volatile(
        "mma.sync.aligned.m16n8k8.row.col.f32.tf32.tf32.f32 "
        "{%0,%1,%2,%3}, {%4,%5,%6,%7}, {%8,%9}, {%0,%1,%2,%3};"
        : "+f"(c[0]), "+f"(c[1]), "+f"(c[2]), "+f"(c[3])
        : "r"(a0), "r"(a1), "r"(a2), "r"(a3), "r"(b0), "r"(b1));
}

/* ================= kernel 0: out[b][c] = out_b[c] ================= */
__global__ void init_out_kernel(const float* __restrict__ ob, float* __restrict__ out) {
    int i = blockIdx.x * 256 + threadIdx.x;
    if (i < B_SZ * C_SZ) out[i] = ob[i % C_SZ];
}

/* ================= kernel 1: selector GEMM + sigmoid (tf32 mma) =================
 * g_fv[m][b] = sigmoid(selW[m,:].x[b,:] + selb[m]); M=49152, N=256, K=128.
 * CTA: 128 m x 64 b. 8 warps = 4 m-warps x 2 n-warps; warp = 2 m-tiles x 4 n-tiles. */
__global__ void __launch_bounds__(256) sel_mma(const float* __restrict__ x,
                                               const float* __restrict__ selW,
                                               const float* __restrict__ selb) {
    extern __shared__ uint32_t sm[];
    uint32_t* As = sm;                 /* 128 x AST */
    uint32_t* Bs = sm + 128 * AST;     /* 64 x AST  */

    const int tid = threadIdx.x;
    const int wid = tid >> 5, lane = tid & 31;
    const int g = lane >> 2, tg = lane & 3;
    const int mw = wid & 3, nw = wid >> 2;
    const int row0 = blockIdx.x * 128, col0 = blockIdx.y * 64;

    float acc[2][4][4];
#pragma unroll
    for (int mi = 0; mi < 2; mi++)
#pragma unroll
        for (int ni = 0; ni < 4; ni++)
#pragma unroll
            for (int q = 0; q < 4; q++) acc[mi][ni][q] = 0.f;

    for (int kt = 0; kt < 2; kt++) {
        __syncthreads();
#pragma unroll
        for (int it = 0; it < 8; it++) {
            int e = tid + it * 256;           /* 2048 float4 */
            int r = e >> 4, q = e & 15;
            float4 v = *(const float4*)(selW + (size_t)(row0 + r) * F_SZ + kt * 64 + q * 4);
            uint4 w = make_uint4(f2tf(v.x), f2tf(v.y), f2tf(v.z), f2tf(v.w));
            *(uint4*)&As[r * AST + q * 4] = w;
        }
#pragma unroll
        for (int it = 0; it < 4; it++) {
            int e = tid + it * 256;           /* 1024 float4 */
            int r = e >> 4, q = e & 15;
            float4 v = *(const float4*)(x + (size_t)(col0 + r) * F_SZ + kt * 64 + q * 4);
            uint4 w = make_uint4(f2tf(v.x), f2tf(v.y), f2tf(v.z), f2tf(v.w));
            *(uint4*)&Bs[r * AST + q * 4] = w;
        }
        __syncthreads();
#pragma unroll
        for (int k0 = 0; k0 < 64; k0 += 8) {
            uint32_t a[2][4], b[4][2];
#pragma unroll
            for (int mi = 0; mi < 2; mi++) {
                int mb = mw * 32 + mi * 16;
                a[mi][0] = As[(mb + g) * AST + k0 + tg];
                a[mi][1] = As[(mb + g + 8) * AST + k0 + tg];
                a[mi][2] = As[(mb + g) * AST + k0 + tg + 4];
                a[mi][3] = As[(mb + g + 8) * AST + k0 + tg + 4];
            }
#pragma unroll
            for (int ni = 0; ni < 4; ni++) {
                int nb = nw * 32 + ni * 8 + g;
                b[ni][0] = Bs[nb * AST + k0 + tg];
                b[ni][1] = Bs[nb * AST + k0 + tg + 4];
            }
#pragma unroll
            for (int mi = 0; mi < 2; mi++)
#pragma unroll
                for (int ni = 0; ni < 4; ni++)
                    mma8(acc[mi][ni], a[mi][0], a[mi][1], a[mi][2], a[mi][3],
                         b[ni][0], b[ni][1]);
        }
    }

    /* epilogue: bias + sigmoid, float2 stores to g_fv */
#pragma unroll
    for (int mi = 0; mi < 2; mi++) {
        int m = row0 + mw * 32 + mi * 16 + g;
        float b0 = selb[m], b1 = selb[m + 8];
#pragma unroll
        for (int ni = 0; ni < 4; ni++) {
            int bcol = col0 + nw * 32 + ni * 8 + tg * 2;
            float2 v0, v1;
            v0.x = 1.f / (1.f + __expf(-(acc[mi][ni][0] + b0)));
            v0.y = 1.f / (1.f + __expf(-(acc[mi][ni][1] + b0)));
            v1.x = 1.f / (1.f + __expf(-(acc[mi][ni][2] + b1)));
            v1.y = 1.f / (1.f + __expf(-(acc[mi][ni][3] + b1)));
            *(float2*)&g_fv[(size_t)m * B_SZ + bcol] = v0;
            *(float2*)&g_fv[(size_t)(m + 8) * B_SZ + bcol] = v1;
        }
    }
}

/* ================= kernel 2: fused leaf + tf32 mma GEMM =================
 * grid = 148. CTA = (b-half of 128 rows, slice of ~111 trees).
 * Per tree: A = leaf[128 b, 64 l] (regs->smem), B = W[112 c(pad), 64 l].
 * 8 warps = 4 m-warps x 2 n-warps; warp = 2 m-tiles x 7 n-tiles (m16n8k8).
 * Double-buffered smem; one syncthreads per tree. atomicAdd epilogue. */
__device__ __forceinline__ void stage_tile(uint32_t* Ab, uint32_t* Bb, int t,
                                           const float* fvb, const float* outW,
                                           int tid, int b_local, int lh) {
    /* ---- leaf tile ---- */
    {
        const float* fp = fvb + (size_t)t * (DEPTHD * B_SZ);
        float p0 = fp[0], p1 = fp[256], p2 = fp[512];
        float p3 = fp[768], p4 = fp[1024], p5 = fp[1280];
        float g0 = lh ? (1.f - p0) : p0;
        float a1[2], a2[4], a3[8], a4[16];
        a1[0] = g0 * p1; a1[1] = g0 * (1.f - p1);
#pragma unroll
        for (int i = 0; i < 2; i++) { a2[2*i] = a1[i] * p2; a2[2*i+1] = a1[i] * (1.f - p2); }
#pragma unroll
        for (int i = 0; i < 4; i++) { a3[2*i] = a2[i] * p3; a3[2*i+1] = a2[i] * (1.f - p3); }
#pragma unroll
        for (int i = 0; i < 8; i++) { a4[2*i] = a3[i] * p4; a4[2*i+1] = a3[i] * (1.f - p4); }
        float q5 = 1.f - p5;
        uint32_t* dst = Ab + b_local * AST + lh * 32;
#pragma unroll
        for (int i = 0; i < 8; i++) {
            uint4 w;
            w.x = f2tf(a4[2*i]     * p5);
            w.y = f2tf(a4[2*i]     * q5);
            w.z = f2tf(a4[2*i + 1] * p5);
            w.w = f2tf(a4[2*i + 1] * q5);
            *(uint4*)(dst + i * 4) = w;
        }
    }
    /* ---- W tile (rows >= C_SZ zeroed) ---- */
    {
        const float* wp = outW + (size_t)t * L_SZ;
#pragma unroll
        for (int it = 0; it < 7; it++) {
            int e = tid + it * 256;           /* N_PAD*16 = 1792 float4 */
            int c = e >> 4, q = e & 15;
            uint4 w;
            if (c < C_SZ) {
                float4 v = *(const float4*)(wp + (size_t)c * KTOT + q * 4);
                w = make_uint4(f2tf(v.x), f2tf(v.y), f2tf(v.z), f2tf(v.w));
            } else {
                w = make_uint4(0u, 0u, 0u, 0u);
            }
            *(uint4*)&Bb[c * AST + q * 4] = w;
        }
    }
}

__global__ void __launch_bounds__(256, 1) accum_mma(const float* __restrict__ outW,
                                                    float* __restrict__ out) {
    extern __shared__ uint32_t sm[];
    const int tid = threadIdx.x;
    const int wid = tid >> 5, lane = tid & 31;
    const int g = lane >> 2, tg = lane & 3;
    const int mw = wid & 3, nw = wid >> 2;
    const int half = blockIdx.x & 1;
    const int slice = blockIdx.x >> 1;
    const int t0 = (slice * NTREE) / NSLICE;
    const int t1 = ((slice + 1) * NTREE) / NSLICE;

    const int b_local = tid >> 1;
    const int lh = tid & 1;
    const float* fvb = g_fv + (size_t)half * 128 + b_local;

    float acc[2][7][4];
#pragma unroll
    for (int mi = 0; mi < 2; mi++)
#pragma unroll
        for (int ni = 0; ni < 7; ni++)
#pragma unroll
            for (int q = 0; q < 4; q++) acc[mi][ni][q] = 0.f;

    uint32_t* A0 = sm;
    uint32_t* A1 = sm + 128 * AST;
    uint32_t* B0 = sm + 2 * 128 * AST;
    uint32_t* B1 = B0 + N_PAD * AST;

    stage_tile(A0, B0, t0, fvb, outW, tid, b_local, lh);
    __syncthreads();

    for (int t = t0; t < t1; t++) {
        const int buf = (t - t0) & 1;
        if (t + 1 < t1)
            stage_tile(buf ? A0 : A1, buf ? B0 : B1, t + 1, fvb, outW, tid, b_local, lh);

        const uint32_t* As = buf ? A1 : A0;
        const uint32_t* Bs = buf ? B1 : B0;
#pragma unroll
        for (int k0 = 0; k0 < 64; k0 += 8) {
            uint32_t a[2][4], b[7][2];
#pragma unroll
            for (int mi = 0; mi < 2; mi++) {
                int mb = mw * 32 + mi * 16;
                a[mi][0] = As[(mb + g) * AST + k0 + tg];
                a[mi][1] = As[(mb + g + 8) * AST + k0 + tg];
                a[mi][2] = As[(mb + g) * AST + k0 + tg + 4];
                a[mi][3] = As[(mb + g + 8) * AST + k0 + tg + 4];
            }
#pragma unroll
            for (int ni = 0; ni < 7; ni++) {
                int nb = nw * 56 + ni * 8 + g;
                b[ni][0] = Bs[nb * AST + k0 + tg];
                b[ni][1] = Bs[nb * AST + k0 + tg + 4];
            }
#pragma unroll
            for (int mi = 0; mi < 2; mi++)
#pragma unroll
                for (int ni = 0; ni < 7; ni++)
                    mma8(acc[mi][ni], a[mi][0], a[mi][1], a[mi][2], a[mi][3],
                         b[ni][0], b[ni][1]);
        }
        __syncthreads();
    }

    /* epilogue: atomicAdd partial sums into out[b][c] */
#pragma unroll
    for (int mi = 0; mi < 2; mi++) {
        int row = half * 128 + mw * 32 + mi * 16 + g;
        float* op0 = out + (size_t)row * C_SZ;
        float* op1 = out + (size_t)(row + 8) * C_SZ;
#pragma unroll
        for (int ni = 0; ni < 7; ni++) {
            int col = nw * 56 + ni * 8 + tg * 2;
            if (col < C_SZ) {
                atomicAdd(op0 + col, acc[mi][ni][0]);
                atomicAdd(op1 + col, acc[mi][ni][2]);
            }
            if (col + 1 < C_SZ) {
                atomicAdd(op0 + col + 1, acc[mi][ni][1]);
                atomicAdd(op1 + col + 1, acc[mi][ni][3]);
            }
        }
    }
}

extern "C" void kernel_launch(void* const* d_in, const int* in_sizes, int n_in,
                              void* d_out, int out_size) {
    const float* x    = (const float*)d_in[0];
    const float* selW = (const float*)d_in[1];
    const float* selb = (const float*)d_in[2];
    const float* outW = (const float*)d_in[3];
    const float* outb = (const float*)d_in[4];
    float* out = (float*)d_out;

    init_out_kernel<<<(B_SZ * C_SZ + 255) / 256, 256>>>(outb, out);

    size_t sel_smem = (size_t)(128 + 64) * AST * 4;                  /* 52224 B */
    cudaFuncSetAttribute(sel_mma, cudaFuncAttributeMaxDynamicSharedMemorySize, (int)sel_smem);
    dim3 g1(384, 4);  /* 49152/128 m-tiles x 256/64 b-tiles */
    sel_mma<<<g1, 256, sel_smem>>>(x, selW, selb);

    size_t acc_smem = (size_t)(2 * 128 + 2 * N_PAD) * AST * 4;       /* 130560 B */
    cudaFuncSetAttribute(accum_mma, cudaFuncAttributeMaxDynamicSharedMemorySize, (int)acc_smem);
    accum_mma<<<2 * NSLICE, 256, acc_smem>>>(outW, out);
}

// round 4
// speedup vs baseline: 6.5111x; 1.7280x over previous
#include <cuda_runtime.h>
#include <cstdint>

#define B_SZ   256
#define F_SZ   128
#define DEPTHD 6
#define C_SZ   100
#define L_SZ   64
#define NTREE  8192
#define KTOT   ((size_t)NTREE * L_SZ)     /* 524288 */
#define NSLICE 148                        /* 296 CTAs = 148 slices x 2 b-halves */
#define N_PAD  112                        /* C padded: 14 n-tiles of 8 */
#define AST    68                         /* sel kernel smem row stride (words) */
#define HST    36                         /* accum smem row stride in half2 words */
#define W_SCALE   512.0f
#define W_INV     0.001953125f            /* 1/512 */

/* scratch: fv[m = tree*6+d][b], 49152 x 256 floats = 50.3 MB */
__device__ float g_fv[NTREE * DEPTHD * B_SZ];

/* ---- helpers ---- */
__device__ __forceinline__ uint32_t f2tf(float f) {
    uint32_t u; asm("cvt.rna.tf32.f32 %0, %1;" : "=r"(u) : "f"(f)); return u;
}
/* pack (lo, hi) floats -> f16x2 reg. PTX: cvt d, a, b => d.lo = b, d.hi = a */
__device__ __forceinline__ uint32_t f2h2(float lo, float hi) {
    uint32_t u; asm("cvt.rn.f16x2.f32 %0, %1, %2;" : "=r"(u) : "f"(hi), "f"(lo)); return u;
}
__device__ __forceinline__ void mma8(float c[4],
                                     uint32_t a0, uint32_t a1, uint32_t a2, uint32_t a3,
                                     uint32_t b0, uint32_t b1) {
    asm volatile(
        "mma.sync.aligned.m16n8k8.row.col.f32.tf32.tf32.f32 "
        "{%0,%1,%2,%3}, {%4,%5,%6,%7}, {%8,%9}, {%0,%1,%2,%3};"
        : "+f"(c[0]), "+f"(c[1]), "+f"(c[2]), "+f"(c[3])
        : "r"(a0), "r"(a1), "r"(a2), "r"(a3), "r"(b0), "r"(b1));
}
__device__ __forceinline__ void mma16(float c[4],
                                      uint32_t a0, uint32_t a1, uint32_t a2, uint32_t a3,
                                      uint32_t b0, uint32_t b1) {
    asm volatile(
        "mma.sync.aligned.m16n8k16.row.col.f32.f16.f16.f32 "
        "{%0,%1,%2,%3}, {%4,%5,%6,%7}, {%8,%9}, {%0,%1,%2,%3};"
        : "+f"(c[0]), "+f"(c[1]), "+f"(c[2]), "+f"(c[3])
        : "r"(a0), "r"(a1), "r"(a2), "r"(a3), "r"(b0), "r"(b1));
}

/* ================= kernel 0: out[b][c] = out_b[c] ================= */
__global__ void init_out_kernel(const float* __restrict__ ob, float* __restrict__ out) {
    int i = blockIdx.x * 256 + threadIdx.x;
    if (i < B_SZ * C_SZ) out[i] = ob[i % C_SZ];
}

/* ================= kernel 1: selector GEMM + sigmoid (tf32 mma, proven) ====== */
__global__ void __launch_bounds__(256) sel_mma(const float* __restrict__ x,
                                               const float* __restrict__ selW,
                                               const float* __restrict__ selb) {
    extern __shared__ uint32_t sm[];
    uint32_t* As = sm;                 /* 128 x AST */
    uint32_t* Bs = sm + 128 * AST;     /* 64 x AST  */

    const int tid = threadIdx.x;
    const int wid = tid >> 5, lane = tid & 31;
    const int g = lane >> 2, tg = lane & 3;
    const int mw = wid & 3, nw = wid >> 2;
    const int row0 = blockIdx.x * 128, col0 = blockIdx.y * 64;

    float acc[2][4][4];
#pragma unroll
    for (int mi = 0; mi < 2; mi++)
#pragma unroll
        for (int ni = 0; ni < 4; ni++)
#pragma unroll
            for (int q = 0; q < 4; q++) acc[mi][ni][q] = 0.f;

    for (int kt = 0; kt < 2; kt++) {
        __syncthreads();
#pragma unroll
        for (int it = 0; it < 8; it++) {
            int e = tid + it * 256;
            int r = e >> 4, q = e & 15;
            float4 v = *(const float4*)(selW + (size_t)(row0 + r) * F_SZ + kt * 64 + q * 4);
            uint4 w = make_uint4(f2tf(v.x), f2tf(v.y), f2tf(v.z), f2tf(v.w));
            *(uint4*)&As[r * AST + q * 4] = w;
        }
#pragma unroll
        for (int it = 0; it < 4; it++) {
            int e = tid + it * 256;
            int r = e >> 4, q = e & 15;
            float4 v = *(const float4*)(x + (size_t)(col0 + r) * F_SZ + kt * 64 + q * 4);
            uint4 w = make_uint4(f2tf(v.x), f2tf(v.y), f2tf(v.z), f2tf(v.w));
            *(uint4*)&Bs[r * AST + q * 4] = w;
        }
        __syncthreads();
#pragma unroll
        for (int k0 = 0; k0 < 64; k0 += 8) {
            uint32_t a[2][4], b[4][2];
#pragma unroll
            for (int mi = 0; mi < 2; mi++) {
                int mb = mw * 32 + mi * 16;
                a[mi][0] = As[(mb + g) * AST + k0 + tg];
                a[mi][1] = As[(mb + g + 8) * AST + k0 + tg];
                a[mi][2] = As[(mb + g) * AST + k0 + tg + 4];
                a[mi][3] = As[(mb + g + 8) * AST + k0 + tg + 4];
            }
#pragma unroll
            for (int ni = 0; ni < 4; ni++) {
                int nb = nw * 32 + ni * 8 + g;
                b[ni][0] = Bs[nb * AST + k0 + tg];
                b[ni][1] = Bs[nb * AST + k0 + tg + 4];
            }
#pragma unroll
            for (int mi = 0; mi < 2; mi++)
#pragma unroll
                for (int ni = 0; ni < 4; ni++)
                    mma8(acc[mi][ni], a[mi][0], a[mi][1], a[mi][2], a[mi][3],
                         b[ni][0], b[ni][1]);
        }
    }
#pragma unroll
    for (int mi = 0; mi < 2; mi++) {
        int m = row0 + mw * 32 + mi * 16 + g;
        float b0 = selb[m], b1 = selb[m + 8];
#pragma unroll
        for (int ni = 0; ni < 4; ni++) {
            int bcol = col0 + nw * 32 + ni * 8 + tg * 2;
            float2 v0, v1;
            v0.x = 1.f / (1.f + __expf(-(acc[mi][ni][0] + b0)));
            v0.y = 1.f / (1.f + __expf(-(acc[mi][ni][1] + b0)));
            v1.x = 1.f / (1.f + __expf(-(acc[mi][ni][2] + b1)));
            v1.y = 1.f / (1.f + __expf(-(acc[mi][ni][3] + b1)));
            *(float2*)&g_fv[(size_t)m * B_SZ + bcol] = v0;
            *(float2*)&g_fv[(size_t)(m + 8) * B_SZ + bcol] = v1;
        }
    }
}

/* ================= kernel 2: fused leaf + fp16 m16n8k16 GEMM =================
 * grid = 296 (148 tree-slices x 2 b-halves), 256 threads, 2 CTAs/SM.
 * A = leaf[128 b, 64 l] in fp16 (half2 per word), B = 512*W[112 c, 64 l] fp16.
 * smem row stride HST=36 words -> fragment LDS banks = 4g+tg+const: conflict-free.
 * 8 warps = 4 mw x 2 nw; warp = 2 m-tiles x 7 n-tiles x 4 k-chunks of 16. */
__device__ __forceinline__ void stage_fp16(uint32_t* Ab, uint32_t* Bb, int t,
                                           const float* fvb, const float* outW,
                                           int tid, int b_local, int lh) {
    /* ---- leaf tile: thread computes 32 leaves (l in [lh*32, lh*32+32)) ---- */
    {
        const float* fp = fvb + (size_t)t * (DEPTHD * B_SZ);
        float p0 = fp[0], p1 = fp[256], p2 = fp[512];
        float p3 = fp[768], p4 = fp[1024], p5 = fp[1280];
        float g0 = lh ? (1.f - p0) : p0;
        float a1[2], a2[4], a3[8], a4[16];
        a1[0] = g0 * p1; a1[1] = g0 * (1.f - p1);
#pragma unroll
        for (int i = 0; i < 2; i++) { a2[2*i] = a1[i] * p2; a2[2*i+1] = a1[i] * (1.f - p2); }
#pragma unroll
        for (int i = 0; i < 4; i++) { a3[2*i] = a2[i] * p3; a3[2*i+1] = a2[i] * (1.f - p3); }
#pragma unroll
        for (int i = 0; i < 8; i++) { a4[2*i] = a3[i] * p4; a4[2*i+1] = a3[i] * (1.f - p4); }
        float q5 = 1.f - p5;
        /* h[k] = half2(a4[k]*p5, a4[k]*q5) = leaves (l=2k even, odd) */
        uint32_t* dst = Ab + b_local * HST + lh * 16;
#pragma unroll
        for (int i = 0; i < 4; i++) {
            uint4 w;
            w.x = f2h2(a4[4*i]     * p5, a4[4*i]     * q5);
            w.y = f2h2(a4[4*i + 1] * p5, a4[4*i + 1] * q5);
            w.z = f2h2(a4[4*i + 2] * p5, a4[4*i + 2] * q5);
            w.w = f2h2(a4[4*i + 3] * p5, a4[4*i + 3] * q5);
            *(uint4*)(dst + i * 4) = w;
        }
    }
    /* ---- W tile: 512*W in fp16; rows >= C_SZ zeroed ---- */
    {
        const float* wp = outW + (size_t)t * L_SZ;
#pragma unroll
        for (int it = 0; it < 7; it++) {
            int e = tid + it * 256;           /* N_PAD*16 = 1792 float4 */
            int c = e >> 4, q = e & 15;
            uint2 w;
            if (c < C_SZ) {
                float4 v = *(const float4*)(wp + (size_t)c * KTOT + q * 4);
                w.x = f2h2(v.x * W_SCALE, v.y * W_SCALE);
                w.y = f2h2(v.z * W_SCALE, v.w * W_SCALE);
            } else {
                w.x = 0u; w.y = 0u;
            }
            *(uint2*)&Bb[c * HST + q * 2] = w;
        }
    }
}

__global__ void __launch_bounds__(256, 2) accum_fp16(const float* __restrict__ outW,
                                                     float* __restrict__ out) {
    extern __shared__ uint32_t sm[];
    uint32_t* A0 = sm;                        /* 128*36 words */
    uint32_t* A1 = A0 + 128 * HST;
    uint32_t* B0 = A1 + 128 * HST;            /* 112*36 words */
    uint32_t* B1 = B0 + N_PAD * HST;

    const int tid = threadIdx.x;
    const int wid = tid >> 5, lane = tid & 31;
    const int g = lane >> 2, tg = lane & 3;
    const int mw = wid & 3, nw = wid >> 2;
    const int half = blockIdx.x & 1;
    const int slice = blockIdx.x >> 1;
    const int t0 = (slice * NTREE) / NSLICE;
    const int t1 = ((slice + 1) * NTREE) / NSLICE;

    const int b_local = tid >> 1;
    const int lh = tid & 1;
    const float* fvb = g_fv + (size_t)half * 128 + b_local;

    float acc[2][7][4];
#pragma unroll
    for (int mi = 0; mi < 2; mi++)
#pragma unroll
        for (int ni = 0; ni < 7; ni++)
#pragma unroll
            for (int q = 0; q < 4; q++) acc[mi][ni][q] = 0.f;

    stage_fp16(A0, B0, t0, fvb, outW, tid, b_local, lh);
    __syncthreads();

    for (int t = t0; t < t1; t++) {
        const int buf = (t - t0) & 1;
        if (t + 1 < t1)
            stage_fp16(buf ? A0 : A1, buf ? B0 : B1, t + 1, fvb, outW, tid, b_local, lh);

        const uint32_t* As = buf ? A1 : A0;
        const uint32_t* Bs = buf ? B1 : B0;
#pragma unroll
        for (int c = 0; c < 4; c++) {         /* k-chunks of 16 */
            uint32_t a[2][4], b[7][2];
#pragma unroll
            for (int mi = 0; mi < 2; mi++) {
                int mb = mw * 32 + mi * 16;
                a[mi][0] = As[(mb + g) * HST + 8 * c + tg];
                a[mi][1] = As[(mb + g + 8) * HST + 8 * c + tg];
                a[mi][2] = As[(mb + g) * HST + 8 * c + tg + 4];
                a[mi][3] = As[(mb + g + 8) * HST + 8 * c + tg + 4];
            }
#pragma unroll
            for (int ni = 0; ni < 7; ni++) {
                int nb = nw * 56 + ni * 8 + g;
                b[ni][0] = Bs[nb * HST + 8 * c + tg];
                b[ni][1] = Bs[nb * HST + 8 * c + tg + 4];
            }
#pragma unroll
            for (int mi = 0; mi < 2; mi++)
#pragma unroll
                for (int ni = 0; ni < 7; ni++)
                    mma16(acc[mi][ni], a[mi][0], a[mi][1], a[mi][2], a[mi][3],
                          b[ni][0], b[ni][1]);
        }
        __syncthreads();
    }

    /* epilogue: atomicAdd (undo the x512 W scale) */
#pragma unroll
    for (int mi = 0; mi < 2; mi++) {
        int row = half * 128 + mw * 32 + mi * 16 + g;
        float* op0 = out + (size_t)row * C_SZ;
        float* op1 = out + (size_t)(row + 8) * C_SZ;
#pragma unroll
        for (int ni = 0; ni < 7; ni++) {
            int col = nw * 56 + ni * 8 + tg * 2;
            if (col < C_SZ) {
                atomicAdd(op0 + col, acc[mi][ni][0] * W_INV);
                atomicAdd(op1 + col, acc[mi][ni][2] * W_INV);
            }
            if (col + 1 < C_SZ) {
                atomicAdd(op0 + col + 1, acc[mi][ni][1] * W_INV);
                atomicAdd(op1 + col + 1, acc[mi][ni][3] * W_INV);
            }
        }
    }
}

extern "C" void kernel_launch(void* const* d_in, const int* in_sizes, int n_in,
                              void* d_out, int out_size) {
    const float* x    = (const float*)d_in[0];
    const float* selW = (const float*)d_in[1];
    const float* selb = (const float*)d_in[2];
    const float* outW = (const float*)d_in[3];
    const float* outb = (const float*)d_in[4];
    float* out = (float*)d_out;

    init_out_kernel<<<(B_SZ * C_SZ + 255) / 256, 256>>>(outb, out);

    size_t sel_smem = (size_t)(128 + 64) * AST * 4;                  /* 52224 B */
    cudaFuncSetAttribute(sel_mma, cudaFuncAttributeMaxDynamicSharedMemorySize, (int)sel_smem);
    dim3 g1(384, 4);
    sel_mma<<<g1, 256, sel_smem>>>(x, selW, selb);

    size_t acc_smem = (size_t)(2 * 128 + 2 * N_PAD) * HST * 4;       /* 69120 B */
    cudaFuncSetAttribute(accum_fp16, cudaFuncAttributeMaxDynamicSharedMemorySize, (int)acc_smem);
    accum_fp16<<<2 * NSLICE, 256, acc_smem>>>(outW, out);
}

// round 5
// speedup vs baseline: 6.8033x; 1.0449x over previous
#include <cuda_runtime.h>
#include <cstdint>

#define B_SZ   256
#define F_SZ   128
#define DEPTHD 6
#define C_SZ   100
#define L_SZ   64
#define NTREE  8192
#define KTOT   ((size_t)NTREE * L_SZ)     /* 524288 */
#define NSLICE 148                        /* one CTA per tree-slice, full B rows */
#define N_PAD  112                        /* C padded: 14 n-tiles of 8 */
#define SST    68                         /* sel smem stride (words), 68 mod 32 = 4 */
#define HST    36                         /* accum smem stride (words), 36 mod 32 = 4 */
#define W_SCALE   512.0f
#define W_INV     0.001953125f            /* 1/512 */

/* scratch: fv[m = tree*6+d][b], 49152 x 256 floats = 50.3 MB */
__device__ float g_fv[NTREE * DEPTHD * B_SZ];

/* ---- helpers ---- */
/* pack (lo, hi) floats -> f16x2 reg. PTX: cvt d, a, b => d.lo = b, d.hi = a */
__device__ __forceinline__ uint32_t f2h2(float lo, float hi) {
    uint32_t u; asm("cvt.rn.f16x2.f32 %0, %1, %2;" : "=r"(u) : "f"(hi), "f"(lo)); return u;
}
__device__ __forceinline__ void mma16(float c[4],
                                      uint32_t a0, uint32_t a1, uint32_t a2, uint32_t a3,
                                      uint32_t b0, uint32_t b1) {
    asm volatile(
        "mma.sync.aligned.m16n8k16.row.col.f32.f16.f16.f32 "
        "{%0,%1,%2,%3}, {%4,%5,%6,%7}, {%8,%9}, {%0,%1,%2,%3};"
        : "+f"(c[0]), "+f"(c[1]), "+f"(c[2]), "+f"(c[3])
        : "r"(a0), "r"(a1), "r"(a2), "r"(a3), "r"(b0), "r"(b1));
}

/* ================= kernel 0: out[b][c] = out_b[c] ================= */
__global__ void init_out_kernel(const float* __restrict__ ob, float* __restrict__ out) {
    int i = blockIdx.x * 256 + threadIdx.x;
    if (i < B_SZ * C_SZ) out[i] = ob[i % C_SZ];
}

/* ================= kernel 1: selector GEMM + sigmoid (fp16 m16n8k16) =========
 * g_fv[m][b] = sigmoid(selW[m,:].x[b,:] + selb[m]); M=49152, N=256, K=128.
 * CTA: 128 m x 64 b, single K=128 staging. 8 warps = 4 mw x 2 nw;
 * warp = 2 m-tiles x 4 n-tiles x 8 k-chunks of 16. */
__global__ void __launch_bounds__(256) sel_fp16(const float* __restrict__ x,
                                                const float* __restrict__ selW,
                                                const float* __restrict__ selb) {
    extern __shared__ uint32_t sm[];
    uint32_t* As = sm;                 /* 128 x SST */
    uint32_t* Bs = sm + 128 * SST;     /* 64 x SST  */

    const int tid = threadIdx.x;
    const int wid = tid >> 5, lane = tid & 31;
    const int g = lane >> 2, tg = lane & 3;
    const int mw = wid & 3, nw = wid >> 2;
    const int row0 = blockIdx.x * 128, col0 = blockIdx.y * 64;

    /* stage A: selW[128 rows x 128 k] -> fp16; 4096 float4 over 256 thr */
#pragma unroll
    for (int it = 0; it < 16; it++) {
        int e = tid + it * 256;
        int r = e >> 5, q = e & 31;
        float4 v = *(const float4*)(selW + (size_t)(row0 + r) * F_SZ + q * 4);
        uint2 w; w.x = f2h2(v.x, v.y); w.y = f2h2(v.z, v.w);
        *(uint2*)&As[r * SST + q * 2] = w;
    }
    /* stage B: x[64 rows x 128 k] -> fp16; 2048 float4 */
#pragma unroll
    for (int it = 0; it < 8; it++) {
        int e = tid + it * 256;
        int r = e >> 5, q = e & 31;
        float4 v = *(const float4*)(x + (size_t)(col0 + r) * F_SZ + q * 4);
        uint2 w; w.x = f2h2(v.x, v.y); w.y = f2h2(v.z, v.w);
        *(uint2*)&Bs[r * SST + q * 2] = w;
    }
    __syncthreads();

    float acc[2][4][4];
#pragma unroll
    for (int mi = 0; mi < 2; mi++)
#pragma unroll
        for (int ni = 0; ni < 4; ni++)
#pragma unroll
            for (int q = 0; q < 4; q++) acc[mi][ni][q] = 0.f;

#pragma unroll
    for (int c = 0; c < 8; c++) {
        uint32_t a[2][4], b[4][2];
#pragma unroll
        for (int mi = 0; mi < 2; mi++) {
            int mb = mw * 32 + mi * 16;
            a[mi][0] = As[(mb + g) * SST + 8 * c + tg];
            a[mi][1] = As[(mb + g + 8) * SST + 8 * c + tg];
            a[mi][2] = As[(mb + g) * SST + 8 * c + tg + 4];
            a[mi][3] = As[(mb + g + 8) * SST + 8 * c + tg + 4];
        }
#pragma unroll
        for (int ni = 0; ni < 4; ni++) {
            int nb = nw * 32 + ni * 8 + g;
            b[ni][0] = Bs[nb * SST + 8 * c + tg];
            b[ni][1] = Bs[nb * SST + 8 * c + tg + 4];
        }
#pragma unroll
        for (int mi = 0; mi < 2; mi++)
#pragma unroll
            for (int ni = 0; ni < 4; ni++)
                mma16(acc[mi][ni], a[mi][0], a[mi][1], a[mi][2], a[mi][3],
                      b[ni][0], b[ni][1]);
    }

#pragma unroll
    for (int mi = 0; mi < 2; mi++) {
        int m = row0 + mw * 32 + mi * 16 + g;
        float b0 = selb[m], b1 = selb[m + 8];
#pragma unroll
        for (int ni = 0; ni < 4; ni++) {
            int bcol = col0 + nw * 32 + ni * 8 + tg * 2;
            float2 v0, v1;
            v0.x = 1.f / (1.f + __expf(-(acc[mi][ni][0] + b0)));
            v0.y = 1.f / (1.f + __expf(-(acc[mi][ni][1] + b0)));
            v1.x = 1.f / (1.f + __expf(-(acc[mi][ni][2] + b1)));
            v1.y = 1.f / (1.f + __expf(-(acc[mi][ni][3] + b1)));
            *(float2*)&g_fv[(size_t)m * B_SZ + bcol] = v0;
            *(float2*)&g_fv[(size_t)(m + 8) * B_SZ + bcol] = v1;
        }
    }
}

/* ================= kernel 2: fused leaf + fp16 GEMM, M=256 =================
 * grid = 148 CTAs (one per tree-slice), 256 threads, 1 CTA/SM.
 * A = leaf[256 b, 64 l] fp16 (thread = one b row), B = 512*W[112 c, 64 l] fp16.
 * 8 warps = 4 mw x 2 nw; warp = 4 m-tiles x 7 n-tiles x 4 k-chunks. */
__device__ __forceinline__ void stage_m256(uint32_t* Ab, uint32_t* Bb, int t,
                                           const float* __restrict__ g_fv_t,
                                           const float* __restrict__ outW, int tid) {
    /* ---- leaf tile: thread = batch row tid, all 64 leaves ---- */
    {
        const float* fp = g_fv_t + (size_t)t * (DEPTHD * B_SZ) + tid;
        float p0 = fp[0], p1 = fp[256], p2 = fp[512];
        float p3 = fp[768], p4 = fp[1024], p5 = fp[1280];
        float q0 = 1.f - p0;
        float a1[2], a2[4], a3[8], a4[16];
        a1[0] = p1; a1[1] = (1.f - p1);
#pragma unroll
        for (int i = 0; i < 2; i++) { a2[2*i] = a1[i] * p2; a2[2*i+1] = a1[i] * (1.f - p2); }
#pragma unroll
        for (int i = 0; i < 4; i++) { a3[2*i] = a2[i] * p3; a3[2*i+1] = a2[i] * (1.f - p3); }
#pragma unroll
        for (int i = 0; i < 8; i++) { a4[2*i] = a3[i] * p4; a4[2*i+1] = a3[i] * (1.f - p4); }
        float q5 = 1.f - p5;
        uint32_t* dst = Ab + tid * HST;
        /* l = 32*s0bit + ... : first 32 leaves scaled by p0, last 32 by q0 */
#pragma unroll
        for (int h = 0; h < 2; h++) {
            float s = h ? q0 : p0;
#pragma unroll
            for (int i = 0; i < 4; i++) {
                float e0 = s * a4[4*i],     e1 = s * a4[4*i + 1];
                float e2 = s * a4[4*i + 2], e3 = s * a4[4*i + 3];
                uint4 w;
                w.x = f2h2(e0 * p5, e0 * q5);
                w.y = f2h2(e1 * p5, e1 * q5);
                w.z = f2h2(e2 * p5, e2 * q5);
                w.w = f2h2(e3 * p5, e3 * q5);
                *(uint4*)(dst + h * 16 + i * 4) = w;
            }
        }
    }
    /* ---- W tile: 512*W fp16; rows >= C_SZ zeroed ---- */
    {
        const float* wp = outW + (size_t)t * L_SZ;
#pragma unroll
        for (int it = 0; it < 7; it++) {
            int e = tid + it * 256;           /* N_PAD*16 = 1792 float4 */
            int c = e >> 4, q = e & 15;
            uint2 w;
            if (c < C_SZ) {
                float4 v = *(const float4*)(wp + (size_t)c * KTOT + q * 4);
                w.x = f2h2(v.x * W_SCALE, v.y * W_SCALE);
                w.y = f2h2(v.z * W_SCALE, v.w * W_SCALE);
            } else {
                w.x = 0u; w.y = 0u;
            }
            *(uint2*)&Bb[c * HST + q * 2] = w;
        }
    }
}

__global__ void __launch_bounds__(256, 1) accum_m256(const float* __restrict__ outW,
                                                     float* __restrict__ out) {
    extern __shared__ uint32_t sm[];
    uint32_t* A0 = sm;                        /* 256*HST words */
    uint32_t* A1 = A0 + 256 * HST;
    uint32_t* B0 = A1 + 256 * HST;            /* 112*HST words */
    uint32_t* B1 = B0 + N_PAD * HST;

    const int tid = threadIdx.x;
    const int wid = tid >> 5, lane = tid & 31;
    const int g = lane >> 2, tg = lane & 3;
    const int mw = wid & 3, nw = wid >> 2;
    const int slice = blockIdx.x;
    const int t0 = (slice * NTREE) / NSLICE;
    const int t1 = ((slice + 1) * NTREE) / NSLICE;

    float acc[4][7][4];
#pragma unroll
    for (int mi = 0; mi < 4; mi++)
#pragma unroll
        for (int ni = 0; ni < 7; ni++)
#pragma unroll
            for (int q = 0; q < 4; q++) acc[mi][ni][q] = 0.f;

    stage_m256(A0, B0, t0, g_fv, outW, tid);
    __syncthreads();

    for (int t = t0; t < t1; t++) {
        const int buf = (t - t0) & 1;
        if (t + 1 < t1)
            stage_m256(buf ? A0 : A1, buf ? B0 : B1, t + 1, g_fv, outW, tid);

        const uint32_t* As = buf ? A1 : A0;
        const uint32_t* Bs = buf ? B1 : B0;
#pragma unroll
        for (int c = 0; c < 4; c++) {
            uint32_t a[4][4], b[7][2];
#pragma unroll
            for (int mi = 0; mi < 4; mi++) {
                int mb = mw * 64 + mi * 16;
                a[mi][0] = As[(mb + g) * HST + 8 * c + tg];
                a[mi][1] = As[(mb + g + 8) * HST + 8 * c + tg];
                a[mi][2] = As[(mb + g) * HST + 8 * c + tg + 4];
                a[mi][3] = As[(mb + g + 8) * HST + 8 * c + tg + 4];
            }
#pragma unroll
            for (int ni = 0; ni < 7; ni++) {
                int nb = nw * 56 + ni * 8 + g;
                b[ni][0] = Bs[nb * HST + 8 * c + tg];
                b[ni][1] = Bs[nb * HST + 8 * c + tg + 4];
            }
#pragma unroll
            for (int mi = 0; mi < 4; mi++)
#pragma unroll
                for (int ni = 0; ni < 7; ni++)
                    mma16(acc[mi][ni], a[mi][0], a[mi][1], a[mi][2], a[mi][3],
                          b[ni][0], b[ni][1]);
        }
        __syncthreads();
    }

    /* epilogue: atomicAdd (undo x512 W scale) */
#pragma unroll
    for (int mi = 0; mi < 4; mi++) {
        int row = mw * 64 + mi * 16 + g;
        float* op0 = out + (size_t)row * C_SZ;
        float* op1 = out + (size_t)(row + 8) * C_SZ;
#pragma unroll
        for (int ni = 0; ni < 7; ni++) {
            int col = nw * 56 + ni * 8 + tg * 2;
            if (col < C_SZ) {
                atomicAdd(op0 + col, acc[mi][ni][0] * W_INV);
                atomicAdd(op1 + col, acc[mi][ni][2] * W_INV);
            }
            if (col + 1 < C_SZ) {
                atomicAdd(op0 + col + 1, acc[mi][ni][1] * W_INV);
                atomicAdd(op1 + col + 1, acc[mi][ni][3] * W_INV);
            }
        }
    }
}

extern "C" void kernel_launch(void* const* d_in, const int* in_sizes, int n_in,
                              void* d_out, int out_size) {
    const float* x    = (const float*)d_in[0];
    const float* selW = (const float*)d_in[1];
    const float* selb = (const float*)d_in[2];
    const float* outW = (const float*)d_in[3];
    const float* outb = (const float*)d_in[4];
    float* out = (float*)d_out;

    init_out_kernel<<<(B_SZ * C_SZ + 255) / 256, 256>>>(outb, out);

    size_t sel_smem = (size_t)(128 + 64) * SST * 4;                  /* 52224 B */
    cudaFuncSetAttribute(sel_fp16, cudaFuncAttributeMaxDynamicSharedMemorySize, (int)sel_smem);
    dim3 g1(384, 4);
    sel_fp16<<<g1, 256, sel_smem>>>(x, selW, selb);

    size_t acc_smem = (size_t)(2 * 256 + 2 * N_PAD) * HST * 4;       /* 105984 B */
    cudaFuncSetAttribute(accum_m256, cudaFuncAttributeMaxDynamicSharedMemorySize, (int)acc_smem);
    accum_m256<<<NSLICE, 256, acc_smem>>>(outW, out);
}

// round 6
// speedup vs baseline: 7.0270x; 1.0329x over previous
#include <cuda_runtime.h>
#include <cstdint>

#define B_SZ   256
#define F_SZ   128
#define DEPTHD 6
#define C_SZ   100
#define L_SZ   64
#define NTREE  8192
#define KTOT   ((size_t)NTREE * L_SZ)     /* 524288 */
#define NSLICE 148                        /* one CTA per tree-slice, full B rows */
#define N_PAD  104                        /* C padded: 13 n-tiles of 8 */
#define SST    68                         /* sel smem stride (words), 68 mod 32 = 4 */
#define HST    36                         /* accum smem stride (words), 36 mod 32 = 4 */
#define W_SCALE   512.0f
#define W_INV     0.001953125f            /* 1/512 */

/* scratch: fv[m = tree*6+d][b], 49152 x 256 floats = 50.3 MB */
__device__ float g_fv[NTREE * DEPTHD * B_SZ];

/* ---- helpers ---- */
/* pack (lo, hi) floats -> f16x2 reg. PTX: cvt d, a, b => d.lo = b, d.hi = a */
__device__ __forceinline__ uint32_t f2h2(float lo, float hi) {
    uint32_t u; asm("cvt.rn.f16x2.f32 %0, %1, %2;" : "=r"(u) : "f"(hi), "f"(lo)); return u;
}
__device__ __forceinline__ void mma16(float c[4],
                                      uint32_t a0, uint32_t a1, uint32_t a2, uint32_t a3,
                                      uint32_t b0, uint32_t b1) {
    asm volatile(
        "mma.sync.aligned.m16n8k16.row.col.f32.f16.f16.f32 "
        "{%0,%1,%2,%3}, {%4,%5,%6,%7}, {%8,%9}, {%0,%1,%2,%3};"
        : "+f"(c[0]), "+f"(c[1]), "+f"(c[2]), "+f"(c[3])
        : "r"(a0), "r"(a1), "r"(a2), "r"(a3), "r"(b0), "r"(b1));
}

/* ================= kernel 0: out[b][c] = out_b[c] ================= */
__global__ void init_out_kernel(const float* __restrict__ ob, float* __restrict__ out) {
    int i = blockIdx.x * 256 + threadIdx.x;
    if (i < B_SZ * C_SZ) out[i] = ob[i % C_SZ];
}

/* ================= kernel 1: selector GEMM + sigmoid (fp16 m16n8k16) =========
 * g_fv[m][b] = sigmoid(selW[m,:].x[b,:] + selb[m]); M=49152, N=256, K=128.
 * CTA: 128 m x 64 b, single K=128 staging. 8 warps = 4 mw x 2 nw;
 * warp = 2 m-tiles x 4 n-tiles x 8 k-chunks of 16. */
__global__ void __launch_bounds__(256) sel_fp16(const float* __restrict__ x,
                                                const float* __restrict__ selW,
                                                const float* __restrict__ selb) {
    extern __shared__ uint32_t sm[];
    uint32_t* As = sm;                 /* 128 x SST */
    uint32_t* Bs = sm + 128 * SST;     /* 64 x SST  */

    const int tid = threadIdx.x;
    const int wid = tid >> 5, lane = tid & 31;
    const int g = lane >> 2, tg = lane & 3;
    const int mw = wid & 3, nw = wid >> 2;
    const int row0 = blockIdx.x * 128, col0 = blockIdx.y * 64;

#pragma unroll
    for (int it = 0; it < 16; it++) {
        int e = tid + it * 256;
        int r = e >> 5, q = e & 31;
        float4 v = *(const float4*)(selW + (size_t)(row0 + r) * F_SZ + q * 4);
        uint2 w; w.x = f2h2(v.x, v.y); w.y = f2h2(v.z, v.w);
        *(uint2*)&As[r * SST + q * 2] = w;
    }
#pragma unroll
    for (int it = 0; it < 8; it++) {
        int e = tid + it * 256;
        int r = e >> 5, q = e & 31;
        float4 v = *(const float4*)(x + (size_t)(col0 + r) * F_SZ + q * 4);
        uint2 w; w.x = f2h2(v.x, v.y); w.y = f2h2(v.z, v.w);
        *(uint2*)&Bs[r * SST + q * 2] = w;
    }
    __syncthreads();

    float acc[2][4][4];
#pragma unroll
    for (int mi = 0; mi < 2; mi++)
#pragma unroll
        for (int ni = 0; ni < 4; ni++)
#pragma unroll
            for (int q = 0; q < 4; q++) acc[mi][ni][q] = 0.f;

#pragma unroll
    for (int c = 0; c < 8; c++) {
        uint32_t a[2][4], b[4][2];
#pragma unroll
        for (int mi = 0; mi < 2; mi++) {
            int mb = mw * 32 + mi * 16;
            a[mi][0] = As[(mb + g) * SST + 8 * c + tg];
            a[mi][1] = As[(mb + g + 8) * SST + 8 * c + tg];
            a[mi][2] = As[(mb + g) * SST + 8 * c + tg + 4];
            a[mi][3] = As[(mb + g + 8) * SST + 8 * c + tg + 4];
        }
#pragma unroll
        for (int ni = 0; ni < 4; ni++) {
            int nb = nw * 32 + ni * 8 + g;
            b[ni][0] = Bs[nb * SST + 8 * c + tg];
            b[ni][1] = Bs[nb * SST + 8 * c + tg + 4];
        }
#pragma unroll
        for (int mi = 0; mi < 2; mi++)
#pragma unroll
            for (int ni = 0; ni < 4; ni++)
                mma16(acc[mi][ni], a[mi][0], a[mi][1], a[mi][2], a[mi][3],
                      b[ni][0], b[ni][1]);
    }

#pragma unroll
    for (int mi = 0; mi < 2; mi++) {
        int m = row0 + mw * 32 + mi * 16 + g;
        float b0 = selb[m], b1 = selb[m + 8];
#pragma unroll
        for (int ni = 0; ni < 4; ni++) {
            int bcol = col0 + nw * 32 + ni * 8 + tg * 2;
            float2 v0, v1;
            v0.x = 1.f / (1.f + __expf(-(acc[mi][ni][0] + b0)));
            v0.y = 1.f / (1.f + __expf(-(acc[mi][ni][1] + b0)));
            v1.x = 1.f / (1.f + __expf(-(acc[mi][ni][2] + b1)));
            v1.y = 1.f / (1.f + __expf(-(acc[mi][ni][3] + b1)));
            *(float2*)&g_fv[(size_t)m * B_SZ + bcol] = v0;
            *(float2*)&g_fv[(size_t)(m + 8) * B_SZ + bcol] = v1;
        }
    }
}

/* ================= kernel 2: fused leaf + fp16 GEMM, M=256, 512 thr =========
 * grid = 148 CTAs (one per tree-slice), 512 threads (16 warps), 1 CTA/SM.
 * A = leaf[256 b, 64 l] fp16, B = 512*W[104 c, 64 l] fp16.
 * 16 warps = 8 mw x 2 nw; warp = 2 m-tiles x {7,6} n-tiles x 4 k-chunks.
 * SMSP k hosts warps {k,k+4,k+8,k+12} = 2 mw x both nw -> 7+6 balanced. */
__device__ __forceinline__ void stage_512(uint32_t* Ab, uint32_t* Bb, int t,
                                          const float* __restrict__ outW,
                                          int tid, int b_local, int lh) {
    /* ---- leaf tile: 2 threads per b row; lh = bit5 of l (d0 bit) ---- */
    {
        const float* fp = g_fv + (size_t)t * (DEPTHD * B_SZ) + b_local;
        float p0 = fp[0], p1 = fp[256], p2 = fp[512];
        float p3 = fp[768], p4 = fp[1024], p5 = fp[1280];
        float g0 = lh ? (1.f - p0) : p0;
        float a1[2], a2[4], a3[8], a4[16];
        a1[0] = g0 * p1; a1[1] = g0 * (1.f - p1);
#pragma unroll
        for (int i = 0; i < 2; i++) { a2[2*i] = a1[i] * p2; a2[2*i+1] = a1[i] * (1.f - p2); }
#pragma unroll
        for (int i = 0; i < 4; i++) { a3[2*i] = a2[i] * p3; a3[2*i+1] = a2[i] * (1.f - p3); }
#pragma unroll
        for (int i = 0; i < 8; i++) { a4[2*i] = a3[i] * p4; a4[2*i+1] = a3[i] * (1.f - p4); }
        float q5 = 1.f - p5;
        uint32_t* dst = Ab + b_local * HST + lh * 16;
#pragma unroll
        for (int i = 0; i < 4; i++) {
            uint4 w;
            w.x = f2h2(a4[4*i]     * p5, a4[4*i]     * q5);
            w.y = f2h2(a4[4*i + 1] * p5, a4[4*i + 1] * q5);
            w.z = f2h2(a4[4*i + 2] * p5, a4[4*i + 2] * q5);
            w.w = f2h2(a4[4*i + 3] * p5, a4[4*i + 3] * q5);
            *(uint4*)(dst + i * 4) = w;
        }
    }
    /* ---- W tile: 512*W fp16; rows >= C_SZ zeroed; 104x16 = 1664 float4 ---- */
    {
        const float* wp = outW + (size_t)t * L_SZ;
#pragma unroll
        for (int it = 0; it < 4; it++) {
            int e = tid + it * 512;
            if (e < N_PAD * 16) {
                int c = e >> 4, q = e & 15;
                uint2 w;
                if (c < C_SZ) {
                    float4 v = *(const float4*)(wp + (size_t)c * KTOT + q * 4);
                    w.x = f2h2(v.x * W_SCALE, v.y * W_SCALE);
                    w.y = f2h2(v.z * W_SCALE, v.w * W_SCALE);
                } else {
                    w.x = 0u; w.y = 0u;
                }
                *(uint2*)&Bb[c * HST + q * 2] = w;
            }
        }
    }
}

template <int NT>
__device__ __forceinline__ void mma_trees(float acc[2][7][4],
                                          const uint32_t* __restrict__ As,
                                          const uint32_t* __restrict__ Bs,
                                          int mw, int nw, int g, int tg) {
#pragma unroll
    for (int c = 0; c < 4; c++) {
        uint32_t a[2][4], b[NT][2];
#pragma unroll
        for (int mi = 0; mi < 2; mi++) {
            int mb = mw * 32 + mi * 16;
            a[mi][0] = As[(mb + g) * HST + 8 * c + tg];
            a[mi][1] = As[(mb + g + 8) * HST + 8 * c + tg];
            a[mi][2] = As[(mb + g) * HST + 8 * c + tg + 4];
            a[mi][3] = As[(mb + g + 8) * HST + 8 * c + tg + 4];
        }
#pragma unroll
        for (int ni = 0; ni < NT; ni++) {
            int nb = nw * 56 + ni * 8 + g;
            b[ni][0] = Bs[nb * HST + 8 * c + tg];
            b[ni][1] = Bs[nb * HST + 8 * c + tg + 4];
        }
#pragma unroll
        for (int mi = 0; mi < 2; mi++)
#pragma unroll
            for (int ni = 0; ni < NT; ni++)
                mma16(acc[mi][ni], a[mi][0], a[mi][1], a[mi][2], a[mi][3],
                      b[ni][0], b[ni][1]);
    }
}

__global__ void __launch_bounds__(512, 1) accum_512(const float* __restrict__ outW,
                                                    float* __restrict__ out) {
    extern __shared__ uint32_t sm[];
    uint32_t* A0 = sm;                        /* 256*HST words */
    uint32_t* A1 = A0 + 256 * HST;
    uint32_t* B0 = A1 + 256 * HST;            /* 104*HST words */
    uint32_t* B1 = B0 + N_PAD * HST;

    const int tid = threadIdx.x;
    const int wid = tid >> 5, lane = tid & 31;
    const int g = lane >> 2, tg = lane & 3;
    const int mw = wid & 7, nw = wid >> 3;
    const int slice = blockIdx.x;
    const int t0 = (slice * NTREE) / NSLICE;
    const int t1 = ((slice + 1) * NTREE) / NSLICE;

    const int b_local = tid >> 1;
    const int lh = tid & 1;

    float acc[2][7][4];
#pragma unroll
    for (int mi = 0; mi < 2; mi++)
#pragma unroll
        for (int ni = 0; ni < 7; ni++)
#pragma unroll
            for (int q = 0; q < 4; q++) acc[mi][ni][q] = 0.f;

    stage_512(A0, B0, t0, outW, tid, b_local, lh);
    __syncthreads();

    for (int t = t0; t < t1; t++) {
        const int buf = (t - t0) & 1;
        if (t + 1 < t1)
            stage_512(buf ? A0 : A1, buf ? B0 : B1, t + 1, outW, tid, b_local, lh);

        const uint32_t* As = buf ? A1 : A0;
        const uint32_t* Bs = buf ? B1 : B0;
        if (nw == 0) mma_trees<7>(acc, As, Bs, mw, nw, g, tg);
        else         mma_trees<6>(acc, As, Bs, mw, nw, g, tg);
        __syncthreads();
    }

    /* epilogue: atomicAdd (undo x512 W scale) */
    const int ntiles = nw ? 6 : 7;
#pragma unroll
    for (int mi = 0; mi < 2; mi++) {
        int row = mw * 32 + mi * 16 + g;
        float* op0 = out + (size_t)row * C_SZ;
        float* op1 = out + (size_t)(row + 8) * C_SZ;
#pragma unroll
        for (int ni = 0; ni < 7; ni++) {
            if (ni >= ntiles) break;
            int col = nw * 56 + ni * 8 + tg * 2;
            if (col < C_SZ) {
                atomicAdd(op0 + col, acc[mi][ni][0] * W_INV);
                atomicAdd(op1 + col, acc[mi][ni][2] * W_INV);
            }
            if (col + 1 < C_SZ) {
                atomicAdd(op0 + col + 1, acc[mi][ni][1] * W_INV);
                atomicAdd(op1 + col + 1, acc[mi][ni][3] * W_INV);
            }
        }
    }
}

extern "C" void kernel_launch(void* const* d_in, const int* in_sizes, int n_in,
                              void* d_out, int out_size) {
    const float* x    = (const float*)d_in[0];
    const float* selW = (const float*)d_in[1];
    const float* selb = (const float*)d_in[2];
    const float* outW = (const float*)d_in[3];
    const float* outb = (const float*)d_in[4];
    float* out = (float*)d_out;

    init_out_kernel<<<(B_SZ * C_SZ + 255) / 256, 256>>>(outb, out);

    size_t sel_smem = (size_t)(128 + 64) * SST * 4;                  /* 52224 B */
    cudaFuncSetAttribute(sel_fp16, cudaFuncAttributeMaxDynamicSharedMemorySize, (int)sel_smem);
    dim3 g1(384, 4);
    sel_fp16<<<g1, 256, sel_smem>>>(x, selW, selb);

    size_t acc_smem = (size_t)(2 * 256 + 2 * N_PAD) * HST * 4;       /* 103680 B */
    cudaFuncSetAttribute(accum_512, cudaFuncAttributeMaxDynamicSharedMemorySize, (int)acc_smem);
    accum_512<<<NSLICE, 512, acc_smem>>>(outW, out);
}